// round 12
// baseline (speedup 1.0000x reference)
#include <cuda_runtime.h>
#include <cuda_fp16.h>
#include <cstdint>

#define NNODES 50000
#define DFEAT  512
#define DHID   1024
#define NCOLS  2048

// ---------------- device scratch ----------------
__device__ __align__(16) __half g_uvh[(size_t)NNODES * NCOLS];   // node activations fp16 [N, 2048]
__device__ __align__(16) __half g_xh[(size_t)NNODES * DFEAT];    // X fp16
__device__ __align__(16) __half g_bh[(size_t)NCOLS * DFEAT];     // W1^T fp16 [2048][512]
__device__ __align__(16) __half g_w2h[DHID];                     // W2 fp16

__device__ __forceinline__ uint32_t smem_u32(const void* p) {
    uint32_t a;
    asm("{ .reg .u64 t; cvta.to.shared.u64 t, %1; cvt.u32.u64 %0, t; }" : "=r"(a) : "l"(p));
    return a;
}

#define LDSM_X4(r0, r1, r2, r3, a) \
    asm volatile("ldmatrix.sync.aligned.m8n8.x4.shared.b16 {%0,%1,%2,%3}, [%4];" \
                 : "=r"(r0), "=r"(r1), "=r"(r2), "=r"(r3) : "r"(a))

#define MMA_F16(d, a, b) \
    asm volatile("mma.sync.aligned.m16n8k16.row.col.f32.f16.f16.f32 " \
                 "{%0,%1,%2,%3}, {%4,%5,%6,%7}, {%8,%9}, {%0,%1,%2,%3};" \
                 : "+f"((d)[0]), "+f"((d)[1]), "+f"((d)[2]), "+f"((d)[3]) \
                 : "r"((a)[0]), "r"((a)[1]), "r"((a)[2]), "r"((a)[3]), "r"((b)[0]), "r"((b)[1]))

#define CP_ASYNC16(sa, ga, sz) \
    asm volatile("cp.async.cg.shared.global [%0], [%1], 16, %2;" :: "r"(sa), "l"(ga), "r"(sz))
#define CP_COMMIT() asm volatile("cp.async.commit_group;" ::: "memory")
#define CP_WAIT2()  asm volatile("cp.async.wait_group 2;" ::: "memory")
#define CP_WAIT0()  asm volatile("cp.async.wait_group 0;" ::: "memory")

__global__ __launch_bounds__(256)
void convert_x_kernel(const float* __restrict__ X) {
    size_t i = (size_t)blockIdx.x * blockDim.x + threadIdx.x;   // float4 index
    const size_t n4 = (size_t)NNODES * DFEAT / 4;
    if (i >= n4) return;
    float4 v = ((const float4*)X)[i];
    unsigned short h0 = __half_as_ushort(__float2half_rn(v.x));
    unsigned short h1 = __half_as_ushort(__float2half_rn(v.y));
    unsigned short h2 = __half_as_ushort(__float2half_rn(v.z));
    unsigned short h3 = __half_as_ushort(__float2half_rn(v.w));
    *(uint2*)(g_xh + i * 4) = make_uint2((uint32_t)h0 | ((uint32_t)h1 << 16),
                                         (uint32_t)h2 | ((uint32_t)h3 << 16));
}

// W1^T fp16:  g_bh[n][k] = W1[half(n)*512 + k][n & 1023];  also W2 -> fp16
__global__ __launch_bounds__(256)
void convert_w_kernel(const float* __restrict__ W1, const float* __restrict__ W2) {
    __shared__ float tile[32][33];
    const int k0 = blockIdx.x * 32;     // k in [0,512)
    const int n0 = blockIdx.y * 32;     // n in [0,2048)
    const int tx = threadIdx.x, ty = threadIdx.y;   // 32 x 8
    const int roff = (n0 >= DHID) ? DFEAT : 0;
#pragma unroll
    for (int j = 0; j < 32; j += 8) {
        int k = k0 + ty + j;
        int n = n0 + tx;
        tile[ty + j][tx] = W1[(size_t)(roff + k) * DHID + (n & (DHID - 1))];
    }
    __syncthreads();
#pragma unroll
    for (int j = 0; j < 32; j += 8) {
        int n = n0 + ty + j;
        int k = k0 + tx;
        g_bh[(size_t)n * DFEAT + k] = __float2half_rn(tile[tx][ty + j]);
    }
    // W2 fp16 (first 4 blocks cover 1024 entries)
    if (blockIdx.y == 0) {
        int idx = blockIdx.x * 256 + ty * 32 + tx;
        if (idx < DHID && blockIdx.x < 4) g_w2h[idx] = __float2half_rn(W2[idx]);
    }
}

// ---------------- HMMA single-pass fp16 GEMM: g_uvh = fp16(X @ [W1_top|W1_bot] (+b1 on u-half))
#define BM 128
#define BN 128
#define BK 32
#define PITCH 80                        // 5 x 16B: conflict-free ldmatrix, no swizzle
#define TILE_B (128 * PITCH)            // 10240 B
#define OFF_AH 0
#define OFF_BH TILE_B
#define STAGE_B (2 * TILE_B)            // 20480 B
#define NSTAGE 4
#define SMEM_DYN (NSTAGE * STAGE_B)     // 81920 B

__global__ __launch_bounds__(256, 2)
void gemm_mma_kernel(const float* __restrict__ b1) {
    extern __shared__ char smem[];
    const uint32_t sbase = smem_u32(smem);
    const int tid = threadIdx.x;
    const int wid = tid >> 5, lane = tid & 31;
    const int col0 = blockIdx.x * BN;
    const int row0 = blockIdx.y * BM;
    const int warp_m = wid & 3;         // 4 m-warps of 32 rows
    const int warp_n = wid >> 2;        // 2 n-warps of 64 cols

    float acc[2][8][4];
#pragma unroll
    for (int mi = 0; mi < 2; mi++)
#pragma unroll
        for (int ni = 0; ni < 8; ni++)
#pragma unroll
            for (int q = 0; q < 4; q++) acc[mi][ni][q] = 0.f;

    const int lr  = tid >> 2;           // 0..63
    const int lc4 = tid & 3;
    auto issue_stage = [&](int kt, int slot) {
        const int k0 = kt * BK;
        const uint32_t sb = sbase + slot * STAGE_B;
#pragma unroll
        for (int h = 0; h < 2; h++) {
            const int r = lr + h * 64;
            const uint32_t so = (uint32_t)(r * PITCH + lc4 * 16);
            const size_t aoff = (size_t)(row0 + r) * DFEAT + k0 + lc4 * 8;
            const int sz = (row0 + r < NNODES) ? 16 : 0;
            CP_ASYNC16(sb + OFF_AH + so, g_xh + aoff, sz);
            const size_t boff = (size_t)(col0 + r) * DFEAT + k0 + lc4 * 8;
            CP_ASYNC16(sb + OFF_BH + so, g_bh + boff, 16);
        }
        CP_COMMIT();
    };

    const uint32_t a_off = (uint32_t)((warp_m * 32 + (lane & 15)) * PITCH + (lane >> 4) * 16);
    const int grp = lane >> 3, r8 = lane & 7;
    const uint32_t b_off = (uint32_t)((warp_n * 64 + ((grp & 2) ? 8 : 0) + r8) * PITCH
                                      + ((grp & 1) ? 16 : 0));

    issue_stage(0, 0);
    issue_stage(1, 1);
    issue_stage(2, 2);

    const int KT = DFEAT / BK;          // 16
    for (int kt = 0; kt < KT; kt++) {
        if (kt + 3 < KT) CP_WAIT2(); else CP_WAIT0();
        __syncthreads();
        if (kt + 3 < KT) issue_stage(kt + 3, (kt + 3) % NSTAGE);

        const uint32_t sb = sbase + (kt % NSTAGE) * STAGE_B;
#pragma unroll
        for (int ks = 0; ks < 2; ks++) {
            const uint32_t kb = ks * 32;
            uint32_t ah[2][4], bh[8][2];
#pragma unroll
            for (int mi = 0; mi < 2; mi++) {
                uint32_t aa = sb + a_off + mi * (16 * PITCH) + kb;
                LDSM_X4(ah[mi][0], ah[mi][1], ah[mi][2], ah[mi][3], aa + OFF_AH);
            }
#pragma unroll
            for (int p = 0; p < 4; p++) {
                uint32_t ba = sb + OFF_BH + b_off + p * (16 * PITCH) + kb;
                LDSM_X4(bh[2 * p][0], bh[2 * p][1], bh[2 * p + 1][0], bh[2 * p + 1][1], ba);
            }
#pragma unroll
            for (int mi = 0; mi < 2; mi++)
#pragma unroll
                for (int ni = 0; ni < 8; ni++)
                    MMA_F16(acc[mi][ni], ah[mi], bh[ni]);
        }
        __syncthreads();
    }

    // --- epilogue: add b1 to u-half, convert to fp16, write g_uvh
    const int r_lo = lane >> 2;
    const int c_lo = (lane & 3) * 2;
#pragma unroll
    for (int mi = 0; mi < 2; mi++) {
        const int row_a = row0 + warp_m * 32 + mi * 16 + r_lo;
        const int row_b = row_a + 8;
#pragma unroll
        for (int ni = 0; ni < 8; ni++) {
            const int col = col0 + warp_n * 64 + ni * 8 + c_lo;
            float bx = 0.f, by = 0.f;
            if (col < DHID) { bx = __ldg(b1 + col); by = __ldg(b1 + col + 1); }
            if (row_a < NNODES)
                *(__half2*)(g_uvh + (size_t)row_a * NCOLS + col) =
                    __floats2half2_rn(acc[mi][ni][0] + bx, acc[mi][ni][1] + by);
            if (row_b < NNODES)
                *(__half2*)(g_uvh + (size_t)row_b * NCOLS + col) =
                    __floats2half2_rn(acc[mi][ni][2] + bx, acc[mi][ni][3] + by);
        }
    }
}

// ---------------- per-edge: out[e] = relu(u'[src] + v[dst]) . W2 + b2  (b1 folded into u')
// TWO warps per edge (64 threads), 4 edges per 256-thread block. Low-reg for full occupancy.
// Index trick: little-endian int64 < 2^31 -> low 32-bit word at idx32[2e] IS the value.
__global__ __launch_bounds__(256)
void edge_kernel(const int* __restrict__ src32, const int* __restrict__ dst32,
                 const float* __restrict__ b2, float* __restrict__ out, int E) {
    __shared__ int s_is64;
    __shared__ float part[8];
    if (threadIdx.x == 0) {
        int orv = 0;
#pragma unroll
        for (int i = 1; i < 16; i += 2) orv |= src32[i] | dst32[i];
        s_is64 = (orv == 0) ? 1 : 0;
    }
    __syncthreads();

    const int wid  = threadIdx.x >> 5;
    const int lane = threadIdx.x & 31;
    const int j    = wid >> 1;          // edge slot in block (0..3)
    const int half = wid & 1;           // which 512-col half of the hidden dim
    const int e = blockIdx.x * 4 + j;

    float acc = 0.f;
    if (e < E) {
        const int sh = s_is64;
        const int s = src32[e << sh];
        const int d = dst32[e << sh];
        const uint4* __restrict__ U = (const uint4*)(g_uvh + (size_t)s * NCOLS) + half * 64;
        const uint4* __restrict__ V = (const uint4*)(g_uvh + (size_t)d * NCOLS + DHID) + half * 64;
        const uint4* __restrict__ W = (const uint4*)g_w2h + half * 64;
#pragma unroll
        for (int i = 0; i < 2; i++) {
            const int c = i * 32 + lane;
            uint4 u = U[c];
            uint4 v = V[c];
            uint4 w = W[c];
            const __half2* uh = (const __half2*)&u;
            const __half2* vh = (const __half2*)&v;
            const __half2* wh = (const __half2*)&w;
#pragma unroll
            for (int q = 0; q < 4; q++) {
                float2 uf = __half22float2(uh[q]);
                float2 vf = __half22float2(vh[q]);
                float2 wf = __half22float2(wh[q]);
                acc += fmaxf(uf.x + vf.x, 0.f) * wf.x
                     + fmaxf(uf.y + vf.y, 0.f) * wf.y;
            }
        }
    }
#pragma unroll
    for (int o = 16; o > 0; o >>= 1) acc += __shfl_xor_sync(0xffffffffu, acc, o);
    if (lane == 0) part[wid] = acc;
    __syncthreads();
    if (threadIdx.x < 4) {
        const int e2 = blockIdx.x * 4 + threadIdx.x;
        if (e2 < E)
            out[e2] = part[2 * threadIdx.x] + part[2 * threadIdx.x + 1] + __ldg(b2);
    }
}

extern "C" void kernel_launch(void* const* d_in, const int* in_sizes, int n_in,
                              void* d_out, int out_size) {
    const float* x   = (const float*)d_in[0];
    const int*   src = (const int*)d_in[1];
    const int*   dst = (const int*)d_in[2];
    const float* W1  = (const float*)d_in[3];
    const float* b1  = (const float*)d_in[4];
    const float* W2  = (const float*)d_in[5];
    const float* b2  = (const float*)d_in[6];
    float* out = (float*)d_out;
    const int E = in_sizes[1];

    cudaFuncSetAttribute(gemm_mma_kernel, cudaFuncAttributeMaxDynamicSharedMemorySize, SMEM_DYN);

    const size_t n4 = (size_t)NNODES * DFEAT / 4;
    convert_x_kernel<<<(unsigned)((n4 + 255) / 256), 256>>>(x);
    convert_w_kernel<<<dim3(DFEAT / 32, NCOLS / 32), dim3(32, 8)>>>(W1, W2);
    gemm_mma_kernel<<<dim3(NCOLS / BN, (NNODES + BM - 1) / BM), 256, SMEM_DYN>>>(b1);
    edge_kernel<<<(E + 3) / 4, 256>>>(src, dst, b2, out, E);
}

// round 13
// speedup vs baseline: 1.0601x; 1.0601x over previous
#include <cuda_runtime.h>
#include <cuda_fp16.h>
#include <cstdint>

#define NNODES 50000
#define DFEAT  512
#define DHID   1024
#define NCOLS  2048

// ---------------- device scratch ----------------
__device__ __align__(16) __half g_uvh[(size_t)NNODES * NCOLS];   // node activations fp16 [N, 2048]
__device__ __align__(16) __half g_xh[(size_t)NNODES * DFEAT];    // X fp16
__device__ __align__(16) __half g_bh[(size_t)NCOLS * DFEAT];     // W1^T fp16 [2048][512]
__device__ __align__(16) __half g_w2h[DHID];                     // W2 fp16

__device__ __forceinline__ uint32_t smem_u32(const void* p) {
    uint32_t a;
    asm("{ .reg .u64 t; cvta.to.shared.u64 t, %1; cvt.u32.u64 %0, t; }" : "=r"(a) : "l"(p));
    return a;
}

#define LDSM_X4(r0, r1, r2, r3, a) \
    asm volatile("ldmatrix.sync.aligned.m8n8.x4.shared.b16 {%0,%1,%2,%3}, [%4];" \
                 : "=r"(r0), "=r"(r1), "=r"(r2), "=r"(r3) : "r"(a))

#define MMA_F16(d, a, b) \
    asm volatile("mma.sync.aligned.m16n8k16.row.col.f32.f16.f16.f32 " \
                 "{%0,%1,%2,%3}, {%4,%5,%6,%7}, {%8,%9}, {%0,%1,%2,%3};" \
                 : "+f"((d)[0]), "+f"((d)[1]), "+f"((d)[2]), "+f"((d)[3]) \
                 : "r"((a)[0]), "r"((a)[1]), "r"((a)[2]), "r"((a)[3]), "r"((b)[0]), "r"((b)[1]))

#define CP_ASYNC16(sa, ga, sz) \
    asm volatile("cp.async.cg.shared.global [%0], [%1], 16, %2;" :: "r"(sa), "l"(ga), "r"(sz))
#define CP_COMMIT() asm volatile("cp.async.commit_group;" ::: "memory")
#define CP_WAIT2()  asm volatile("cp.async.wait_group 2;" ::: "memory")
#define CP_WAIT0()  asm volatile("cp.async.wait_group 0;" ::: "memory")

__global__ __launch_bounds__(256)
void convert_x_kernel(const float* __restrict__ X) {
    size_t i = (size_t)blockIdx.x * blockDim.x + threadIdx.x;   // float4 index
    const size_t n4 = (size_t)NNODES * DFEAT / 4;
    if (i >= n4) return;
    float4 v = ((const float4*)X)[i];
    unsigned short h0 = __half_as_ushort(__float2half_rn(v.x));
    unsigned short h1 = __half_as_ushort(__float2half_rn(v.y));
    unsigned short h2 = __half_as_ushort(__float2half_rn(v.z));
    unsigned short h3 = __half_as_ushort(__float2half_rn(v.w));
    *(uint2*)(g_xh + i * 4) = make_uint2((uint32_t)h0 | ((uint32_t)h1 << 16),
                                         (uint32_t)h2 | ((uint32_t)h3 << 16));
}

// W1^T fp16:  g_bh[n][k] = W1[half(n)*512 + k][n & 1023];  also W2 -> fp16
__global__ __launch_bounds__(256)
void convert_w_kernel(const float* __restrict__ W1, const float* __restrict__ W2) {
    __shared__ float tile[32][33];
    const int k0 = blockIdx.x * 32;     // k in [0,512)
    const int n0 = blockIdx.y * 32;     // n in [0,2048)
    const int tx = threadIdx.x, ty = threadIdx.y;   // 32 x 8
    const int roff = (n0 >= DHID) ? DFEAT : 0;
#pragma unroll
    for (int j = 0; j < 32; j += 8) {
        int k = k0 + ty + j;
        int n = n0 + tx;
        tile[ty + j][tx] = W1[(size_t)(roff + k) * DHID + (n & (DHID - 1))];
    }
    __syncthreads();
#pragma unroll
    for (int j = 0; j < 32; j += 8) {
        int n = n0 + ty + j;
        int k = k0 + tx;
        g_bh[(size_t)n * DFEAT + k] = __float2half_rn(tile[tx][ty + j]);
    }
    // W2 fp16 (first 4 blocks cover 1024 entries)
    if (blockIdx.y == 0) {
        int idx = blockIdx.x * 256 + ty * 32 + tx;
        if (idx < DHID && blockIdx.x < 4) g_w2h[idx] = __float2half_rn(W2[idx]);
    }
}

// ---------------- HMMA single-pass fp16 GEMM: g_uvh = fp16(X @ [W1_top|W1_bot] (+b1 on u-half))
#define BM 128
#define BN 128
#define BK 32
#define PITCH 80                        // 5 x 16B: conflict-free ldmatrix, no swizzle
#define TILE_B (128 * PITCH)            // 10240 B
#define OFF_AH 0
#define OFF_BH TILE_B
#define STAGE_B (2 * TILE_B)            // 20480 B
#define NSTAGE 4
#define SMEM_DYN (NSTAGE * STAGE_B)     // 81920 B

__global__ __launch_bounds__(256, 2)
void gemm_mma_kernel(const float* __restrict__ b1) {
    extern __shared__ char smem[];
    const uint32_t sbase = smem_u32(smem);
    const int tid = threadIdx.x;
    const int wid = tid >> 5, lane = tid & 31;
    const int col0 = blockIdx.x * BN;
    const int row0 = blockIdx.y * BM;
    const int warp_m = wid & 3;         // 4 m-warps of 32 rows
    const int warp_n = wid >> 2;        // 2 n-warps of 64 cols

    float acc[2][8][4];
#pragma unroll
    for (int mi = 0; mi < 2; mi++)
#pragma unroll
        for (int ni = 0; ni < 8; ni++)
#pragma unroll
            for (int q = 0; q < 4; q++) acc[mi][ni][q] = 0.f;

    const int lr  = tid >> 2;           // 0..63
    const int lc4 = tid & 3;
    auto issue_stage = [&](int kt, int slot) {
        const int k0 = kt * BK;
        const uint32_t sb = sbase + slot * STAGE_B;
#pragma unroll
        for (int h = 0; h < 2; h++) {
            const int r = lr + h * 64;
            const uint32_t so = (uint32_t)(r * PITCH + lc4 * 16);
            const size_t aoff = (size_t)(row0 + r) * DFEAT + k0 + lc4 * 8;
            const int sz = (row0 + r < NNODES) ? 16 : 0;
            CP_ASYNC16(sb + OFF_AH + so, g_xh + aoff, sz);
            const size_t boff = (size_t)(col0 + r) * DFEAT + k0 + lc4 * 8;
            CP_ASYNC16(sb + OFF_BH + so, g_bh + boff, 16);
        }
        CP_COMMIT();
    };

    const uint32_t a_off = (uint32_t)((warp_m * 32 + (lane & 15)) * PITCH + (lane >> 4) * 16);
    const int grp = lane >> 3, r8 = lane & 7;
    const uint32_t b_off = (uint32_t)((warp_n * 64 + ((grp & 2) ? 8 : 0) + r8) * PITCH
                                      + ((grp & 1) ? 16 : 0));

    issue_stage(0, 0);
    issue_stage(1, 1);
    issue_stage(2, 2);

    const int KT = DFEAT / BK;          // 16
    for (int kt = 0; kt < KT; kt++) {
        if (kt + 3 < KT) CP_WAIT2(); else CP_WAIT0();
        __syncthreads();
        if (kt + 3 < KT) issue_stage(kt + 3, (kt + 3) % NSTAGE);

        const uint32_t sb = sbase + (kt % NSTAGE) * STAGE_B;
#pragma unroll
        for (int ks = 0; ks < 2; ks++) {
            const uint32_t kb = ks * 32;
            uint32_t ah[2][4], bh[8][2];
#pragma unroll
            for (int mi = 0; mi < 2; mi++) {
                uint32_t aa = sb + a_off + mi * (16 * PITCH) + kb;
                LDSM_X4(ah[mi][0], ah[mi][1], ah[mi][2], ah[mi][3], aa + OFF_AH);
            }
#pragma unroll
            for (int p = 0; p < 4; p++) {
                uint32_t ba = sb + OFF_BH + b_off + p * (16 * PITCH) + kb;
                LDSM_X4(bh[2 * p][0], bh[2 * p][1], bh[2 * p + 1][0], bh[2 * p + 1][1], ba);
            }
#pragma unroll
            for (int mi = 0; mi < 2; mi++)
#pragma unroll
                for (int ni = 0; ni < 8; ni++)
                    MMA_F16(acc[mi][ni], ah[mi], bh[ni]);
        }
        __syncthreads();
    }

    // --- epilogue: add b1 to u-half, convert to fp16, write g_uvh
    const int r_lo = lane >> 2;
    const int c_lo = (lane & 3) * 2;
#pragma unroll
    for (int mi = 0; mi < 2; mi++) {
        const int row_a = row0 + warp_m * 32 + mi * 16 + r_lo;
        const int row_b = row_a + 8;
#pragma unroll
        for (int ni = 0; ni < 8; ni++) {
            const int col = col0 + warp_n * 64 + ni * 8 + c_lo;
            float bx = 0.f, by = 0.f;
            if (col < DHID) { bx = __ldg(b1 + col); by = __ldg(b1 + col + 1); }
            if (row_a < NNODES)
                *(__half2*)(g_uvh + (size_t)row_a * NCOLS + col) =
                    __floats2half2_rn(acc[mi][ni][0] + bx, acc[mi][ni][1] + by);
            if (row_b < NNODES)
                *(__half2*)(g_uvh + (size_t)row_b * NCOLS + col) =
                    __floats2half2_rn(acc[mi][ni][2] + bx, acc[mi][ni][3] + by);
        }
    }
}

// ---------------- per-edge: out[e] = relu(u'[src] + v[dst]) . W2 + b2  (b1 folded into u')
// One warp per edge (R10 structure), half2 relu math, fp32 accumulation.
__global__ __launch_bounds__(256)
void edge_kernel(const int* __restrict__ src32, const int* __restrict__ dst32,
                 const float* __restrict__ b2, float* __restrict__ out, int E) {
    __shared__ int s_is64;
    if (threadIdx.x == 0) {
        int orv = 0;
#pragma unroll
        for (int i = 1; i < 16; i += 2) orv |= src32[i] | dst32[i];
        s_is64 = (orv == 0) ? 1 : 0;
    }
    __syncthreads();

    const int wid  = threadIdx.x >> 5;
    const int lane = threadIdx.x & 31;
    const int e = blockIdx.x * 8 + wid;
    if (e >= E) return;

    // int64 little-endian values < 2^31: low word at idx32[2e] IS the index
    const int sh = s_is64;
    const int s = src32[(size_t)e << sh];
    const int d = dst32[(size_t)e << sh];

    const uint4* __restrict__ U = (const uint4*)(g_uvh + (size_t)s * NCOLS);
    const uint4* __restrict__ V = (const uint4*)(g_uvh + (size_t)d * NCOLS + DHID);
    const uint4* __restrict__ W = (const uint4*)g_w2h;

    const __half2 z2 = __float2half2_rn(0.f);
    float acc = 0.f;
#pragma unroll
    for (int i = 0; i < 4; i++) {
        const int c = i * 32 + lane;        // uint4 index: 8 halves
        uint4 u = U[c];
        uint4 v = V[c];
        uint4 w = W[c];
        const __half2* uh = (const __half2*)&u;
        const __half2* vh = (const __half2*)&v;
        const __half2* wh = (const __half2*)&w;
#pragma unroll
        for (int j = 0; j < 4; j++) {
            __half2 h = __hmax2(__hadd2(uh[j], vh[j]), z2);   // relu(u+v) in fp16
            float2 hf = __half22float2(h);
            float2 wf = __half22float2(wh[j]);
            acc = fmaf(hf.x, wf.x, acc);
            acc = fmaf(hf.y, wf.y, acc);
        }
    }
#pragma unroll
    for (int o = 16; o > 0; o >>= 1) acc += __shfl_xor_sync(0xffffffffu, acc, o);
    if (lane == 0) out[e] = acc + __ldg(b2);
}

extern "C" void kernel_launch(void* const* d_in, const int* in_sizes, int n_in,
                              void* d_out, int out_size) {
    const float* x   = (const float*)d_in[0];
    const int*   src = (const int*)d_in[1];
    const int*   dst = (const int*)d_in[2];
    const float* W1  = (const float*)d_in[3];
    const float* b1  = (const float*)d_in[4];
    const float* W2  = (const float*)d_in[5];
    const float* b2  = (const float*)d_in[6];
    float* out = (float*)d_out;
    const int E = in_sizes[1];

    cudaFuncSetAttribute(gemm_mma_kernel, cudaFuncAttributeMaxDynamicSharedMemorySize, SMEM_DYN);

    const size_t n4 = (size_t)NNODES * DFEAT / 4;
    convert_x_kernel<<<(unsigned)((n4 + 255) / 256), 256>>>(x);
    convert_w_kernel<<<dim3(DFEAT / 32, NCOLS / 32), dim3(32, 8)>>>(W1, W2);
    gemm_mma_kernel<<<dim3(NCOLS / BN, (NNODES + BM - 1) / BM), 256, SMEM_DYN>>>(b1);
    edge_kernel<<<(E + 7) / 8, 256>>>(src, dst, b2, out, E);
}